// round 11
// baseline (speedup 1.0000x reference)
#include <cuda_runtime.h>
#include <cuda_bf16.h>

// FINAL (held, R10 confirmed). The reference network mathematically collapses:
// the GNN "layernorm" is over a feature axis of size 1, so
// (y-mean)/sqrt(var+eps)==0 exactly and h == ln_bias[l] after each propagation
// layer, independent of everything upstream (hash grids, SIREN trunk, member
// heads, 2M graph edges).
// Output = softplus(ln_bias[1,0]) * sigmoid((1 - psi_n) * 50), elementwise.
//
// Saturation established R1-R10. Byte-identical source benched five times:
// 4.512 / 4.576 / 4.608 / 4.544 / 4.576 us (mean 4.56, sigma ~0.04); ncu
// kernel-internal time for the same binary varied 3.78-4.35us — both
// measurements are noise around fixed floors. All pipes <1%; duration is
// launch overhead (T_ovh ~5000cyc + one DRAM round-trip). Shape space fully
// characterized: 64x256: 6.9 | 128x128: ~4.6 | 256x64: ~4.55 | 512x32: 4.61.
// Pinned best-mean point: 256 CTAs x 64 thr, __expf/__fdividef, 16 regs.

__global__ __launch_bounds__(64, 32)
void collapsed_forward_kernel(const float* __restrict__ psi_n,
                              const float* __restrict__ ln_bias,
                              float* __restrict__ out) {
    int i = blockIdx.x * 64 + threadIdx.x;   // exactly 16384 threads = n/4

    // Issue both loads immediately so their DRAM latencies overlap.
    float4 p = reinterpret_cast<const float4*>(psi_n)[i];
    float b = __ldg(&ln_bias[1]);

    float refined = __logf(1.0f + __expf(b));   // softplus(ln_bias[1])

    // refined * sigmoid((1-p)*50); sigmoid arg negated: (p-1)*50 = fma(p,50,-50)
    float4 r;
    r.x = __fdividef(refined, 1.0f + __expf(fmaf(p.x, 50.0f, -50.0f)));
    r.y = __fdividef(refined, 1.0f + __expf(fmaf(p.y, 50.0f, -50.0f)));
    r.z = __fdividef(refined, 1.0f + __expf(fmaf(p.z, 50.0f, -50.0f)));
    r.w = __fdividef(refined, 1.0f + __expf(fmaf(p.w, 50.0f, -50.0f)));
    reinterpret_cast<float4*>(out)[i] = r;
}

extern "C" void kernel_launch(void* const* d_in, const int* in_sizes, int n_in,
                              void* d_out, int out_size) {
    const float* psi_n   = (const float*)d_in[2];
    const float* ln_bias = (const float*)d_in[25];
    float* out = (float*)d_out;

    int n4 = out_size / 4;          // 16384
    int blocks = n4 / 64;           // 256 CTAs x 64 threads, exact cover
    collapsed_forward_kernel<<<blocks, 64>>>(psi_n, ln_bias, out);
}

// round 12
// speedup vs baseline: 1.5141x; 1.5141x over previous
#include <cuda_runtime.h>
#include <cuda_bf16.h>

// FINAL (held). The reference network mathematically collapses: the GNN
// "layernorm" is over a feature axis of size 1, so (y-mean)/sqrt(var+eps)==0
// exactly and h == ln_bias[l] after each propagation layer, independent of
// everything upstream (hash grids, SIREN trunk, member heads, 2M graph edges).
// Output = softplus(ln_bias[1,0]) * sigmoid((1 - psi_n) * 50), elementwise.
//
// Measurement model (R1-R11): ncu kernel-internal time 3.78-4.35us for this
// binary, every pipe <1% — pure launch-overhead floor. The BENCH number is
// BIMODAL for byte-identical source: common mode ~4.55us (4.512/4.544/4.576/
// 4.576/4.608), occasional mode ~6.9us (R11: 6.880) — one extra ~2.3us
// quantum of harness replay/calibration overhead. R1/R2's 6.9 with a 64x256
// grid was this slow mode, not a shape effect: shape, body, and regs never
// moved the kernel time. No .cu-level lever exists for either mode. Holding
// the pinned configuration: 256 CTAs x 64 thr, __expf/__fdividef, 16 regs.

__global__ __launch_bounds__(64, 32)
void collapsed_forward_kernel(const float* __restrict__ psi_n,
                              const float* __restrict__ ln_bias,
                              float* __restrict__ out) {
    int i = blockIdx.x * 64 + threadIdx.x;   // exactly 16384 threads = n/4

    // Issue both loads immediately so their DRAM latencies overlap.
    float4 p = reinterpret_cast<const float4*>(psi_n)[i];
    float b = __ldg(&ln_bias[1]);

    float refined = __logf(1.0f + __expf(b));   // softplus(ln_bias[1])

    // refined * sigmoid((1-p)*50); sigmoid arg negated: (p-1)*50 = fma(p,50,-50)
    float4 r;
    r.x = __fdividef(refined, 1.0f + __expf(fmaf(p.x, 50.0f, -50.0f)));
    r.y = __fdividef(refined, 1.0f + __expf(fmaf(p.y, 50.0f, -50.0f)));
    r.z = __fdividef(refined, 1.0f + __expf(fmaf(p.z, 50.0f, -50.0f)));
    r.w = __fdividef(refined, 1.0f + __expf(fmaf(p.w, 50.0f, -50.0f)));
    reinterpret_cast<float4*>(out)[i] = r;
}

extern "C" void kernel_launch(void* const* d_in, const int* in_sizes, int n_in,
                              void* d_out, int out_size) {
    const float* psi_n   = (const float*)d_in[2];
    const float* ln_bias = (const float*)d_in[25];
    float* out = (float*)d_out;

    int n4 = out_size / 4;          // 16384
    int blocks = n4 / 64;           // 256 CTAs x 64 threads, exact cover
    collapsed_forward_kernel<<<blocks, 64>>>(psi_n, ln_bias, out);
}